// round 2
// baseline (speedup 1.0000x reference)
#include <cuda_runtime.h>

#define B_ 4
#define D_ 256
#define L_ 4096
#define NTOK (B_*L_)          // 16384 tokens
#define KC 8192               // codes
#define NQ (B_*D_*L_)         // 4194304 output elems for q

#define MT 128                // token tile
#define NT 128                // code tile
#define DCH 64                // d-chunk
#define SMEM_BYTES ((D_*MT + DCH*NT) * 4)   // 160 KB

// ---- scratch (device globals; no allocation allowed) ----
__device__ float g_xt[NTOK * D_];   // transposed tokens, then normalized in-place
__device__ float g_cn[KC * D_];     // normalized codebook
__device__ int   g_idx[NTOK];
__device__ float g_part[4096];

// ---------------------------------------------------------------------------
__device__ __forceinline__ float blk_reduce_sum(float v, float* sbuf) {
    #pragma unroll
    for (int o = 16; o; o >>= 1) v += __shfl_xor_sync(0xffffffffu, v, o);
    int w = threadIdx.x >> 5;
    if ((threadIdx.x & 31) == 0) sbuf[w] = v;
    __syncthreads();
    if (threadIdx.x < 32) {
        v = (threadIdx.x < (blockDim.x >> 5)) ? sbuf[threadIdx.x] : 0.f;
        #pragma unroll
        for (int o = 4; o; o >>= 1) v += __shfl_xor_sync(0xffffffffu, v, o);
        if (threadIdx.x == 0) sbuf[0] = v;
    }
    __syncthreads();
    return sbuf[0];
}

// ---- [B,D,L] -> [N,D] transpose (coalesced both sides) ---------------------
__global__ void k_transpose(const float* __restrict__ x) {
    __shared__ float tile[32][33];
    int b  = blockIdx.z;
    int d0 = blockIdx.y * 32;
    int l0 = blockIdx.x * 32;
    #pragma unroll
    for (int i = threadIdx.y; i < 32; i += 8)
        tile[i][threadIdx.x] = x[((size_t)b * D_ + (d0 + i)) * L_ + l0 + threadIdx.x];
    __syncthreads();
    #pragma unroll
    for (int i = threadIdx.y; i < 32; i += 8)
        g_xt[((size_t)(b * L_ + l0 + i)) * D_ + d0 + threadIdx.x] = tile[threadIdx.x][i];
}

// ---- row L2-normalize (256 threads == D) -----------------------------------
__global__ void k_normalize(const float* __restrict__ in, float* __restrict__ out) {
    __shared__ float sbuf[8];
    size_t r = blockIdx.x;
    int t = threadIdx.x;
    float v = in[r * D_ + t];
    float s = blk_reduce_sum(v * v, sbuf);
    float inv = 1.f / fmaxf(sqrtf(s), 1e-12f);
    out[r * D_ + t] = v * inv;
}

// ---- fused GEMM (16384 x 8192 x 256) + per-token argmax --------------------
__global__ void __launch_bounds__(256, 1) k_gemm_argmax() {
    extern __shared__ float smem[];
    float* tok_s  = smem;               // [D_][MT]  (128 KB)
    float* code_s = smem + D_ * MT;     // [DCH][NT] (32 KB)

    const int tid = threadIdx.x;
    const int tx = tid & 15, ty = tid >> 4;
    const int m0 = blockIdx.x * MT;

    // resident token tile, [d][m] layout
    for (int i = tid; i < MT * (D_ / 4); i += 256) {
        int m  = i >> 6;            // D_/4 == 64
        int d4 = i & 63;
        float4 v = *(const float4*)(g_xt + (size_t)(m0 + m) * D_ + d4 * 4);
        tok_s[(d4 * 4 + 0) * MT + m] = v.x;
        tok_s[(d4 * 4 + 1) * MT + m] = v.y;
        tok_s[(d4 * 4 + 2) * MT + m] = v.z;
        tok_s[(d4 * 4 + 3) * MT + m] = v.w;
    }

    float bestv[8]; int besti[8];
    #pragma unroll
    for (int i = 0; i < 8; i++) { bestv[i] = -2.f; besti[i] = 0; }

    for (int k0 = 0; k0 < KC; k0 += NT) {
        float acc[8][8];
        #pragma unroll
        for (int i = 0; i < 8; i++)
            #pragma unroll
            for (int j = 0; j < 8; j++) acc[i][j] = 0.f;

        for (int dc = 0; dc < D_; dc += DCH) {
            __syncthreads();
            for (int i = tid; i < NT * (DCH / 4); i += 256) {
                int n  = i >> 4;    // DCH/4 == 16
                int d4 = i & 15;
                float4 v = *(const float4*)(g_cn + (size_t)(k0 + n) * D_ + dc + d4 * 4);
                code_s[(d4 * 4 + 0) * NT + n] = v.x;
                code_s[(d4 * 4 + 1) * NT + n] = v.y;
                code_s[(d4 * 4 + 2) * NT + n] = v.z;
                code_s[(d4 * 4 + 3) * NT + n] = v.w;
            }
            __syncthreads();
            #pragma unroll 8
            for (int d = 0; d < DCH; d++) {
                float ta[8], tb[8];
                const float* tp = tok_s + (dc + d) * MT + ty * 8;
                *(float4*)(ta)     = *(const float4*)(tp);
                *(float4*)(ta + 4) = *(const float4*)(tp + 4);
                const float* cp = code_s + d * NT + tx * 8;
                *(float4*)(tb)     = *(const float4*)(cp);
                *(float4*)(tb + 4) = *(const float4*)(cp + 4);
                #pragma unroll
                for (int i = 0; i < 8; i++)
                    #pragma unroll
                    for (int j = 0; j < 8; j++)
                        acc[i][j] = fmaf(ta[i], tb[j], acc[i][j]);
            }
        }
        // fold this code tile into the running per-token max (first-index tiebreak)
        #pragma unroll
        for (int i = 0; i < 8; i++)
            #pragma unroll
            for (int j = 0; j < 8; j++) {
                int k = k0 + tx * 8 + j;
                if (acc[i][j] > bestv[i] ||
                    (acc[i][j] == bestv[i] && k < besti[i])) {
                    bestv[i] = acc[i][j]; besti[i] = k;
                }
            }
    }

    // cross-thread (over tx) argmax reduce; reuse code_s (8192 floats avail)
    __syncthreads();
    float* rv = code_s;                       // [128][16]
    int*   ri = (int*)(code_s + 128 * 16);    // [128][16]
    #pragma unroll
    for (int i = 0; i < 8; i++) {
        rv[(ty * 8 + i) * 16 + tx] = bestv[i];
        ri[(ty * 8 + i) * 16 + tx] = besti[i];
    }
    __syncthreads();
    if (tid < MT) {
        float bv = -3.f; int bi = 0;
        #pragma unroll
        for (int t = 0; t < 16; t++) {
            float v = rv[tid * 16 + t]; int ix = ri[tid * 16 + t];
            if (v > bv || (v == bv && ix < bi)) { bv = v; bi = ix; }
        }
        g_idx[m0 + tid] = bi;
    }
}

// ---- output gather + per-block loss partials -------------------------------
// grid (B_*D_, 4), block 256; each thread: 4 consecutive l via float4
__global__ void k_out_loss(const float* __restrict__ x, float* __restrict__ out) {
    __shared__ float sbuf[8];
    int b = blockIdx.x >> 8;
    int d = blockIdx.x & 255;
    int l = blockIdx.y * 1024 + threadIdx.x * 4;
    size_t base = ((size_t)b * D_ + d) * L_;

    float4 xv = *(const float4*)(x + base + l);
    int4  iv  = *(const int4*)(g_idx + b * L_ + l);
    float q0 = g_cn[(size_t)iv.x * D_ + d];
    float q1 = g_cn[(size_t)iv.y * D_ + d];
    float q2 = g_cn[(size_t)iv.z * D_ + d];
    float q3 = g_cn[(size_t)iv.w * D_ + d];
    *(float4*)(out + base + l) = make_float4(q0, q1, q2, q3);

    float e0 = q0 - xv.x, e1 = q1 - xv.y, e2 = q2 - xv.z, e3 = q3 - xv.w;
    float s = blk_reduce_sum(e0*e0 + e1*e1 + e2*e2 + e3*e3, sbuf);
    if (threadIdx.x == 0) g_part[blockIdx.y * 1024 + blockIdx.x] = s;
}

__global__ void k_loss_final(float* __restrict__ out, int pos) {
    __shared__ float sbuf[8];
    float s = 0.f;
    for (int i = threadIdx.x; i < 4096; i += 256) s += g_part[i];
    s = blk_reduce_sum(s, sbuf);
    if (threadIdx.x == 0)
        out[pos] = 0.25f * s / (float)((size_t)NTOK * D_);
}

// ---------------------------------------------------------------------------
extern "C" void kernel_launch(void* const* d_in, const int* in_sizes, int n_in,
                              void* d_out, int out_size) {
    const float* x  = (const float*)d_in[0];   // [4,256,4096]
    const float* cb = (const float*)d_in[1];   // [8192,256]
    float* out = (float*)d_out;

    cudaFuncSetAttribute(k_gemm_argmax,
                         cudaFuncAttributeMaxDynamicSharedMemorySize, SMEM_BYTES);

    void *p_xt = nullptr, *p_cn = nullptr;
    cudaGetSymbolAddress(&p_xt, g_xt);
    cudaGetSymbolAddress(&p_cn, g_cn);

    k_transpose<<<dim3(L_ / 32, D_ / 32, B_), dim3(32, 8)>>>(x);
    k_normalize<<<NTOK, 256>>>((const float*)p_xt, (float*)p_xt);  // in-place
    k_normalize<<<KC, 256>>>(cb, (float*)p_cn);
    k_gemm_argmax<<<NTOK / MT, 256, SMEM_BYTES>>>();
    k_out_loss<<<dim3(B_ * D_, 4), 256>>>(x, out);
    if (out_size > NQ)
        k_loss_final<<<1, 256>>>(out, out_size - 1);
}

// round 3
// speedup vs baseline: 1.6237x; 1.6237x over previous
#include <cuda_runtime.h>

#define B_ 4
#define D_ 256
#define L_ 4096
#define NTOK (B_*L_)          // 16384 tokens
#define KC 8192               // codes
#define NQ (B_*D_*L_)         // 4194304 output elems for q

#define MT 128                // token tile (per CTA)
#define NT 256                // code tile (per CTA, as 128 f32x2 pairs)
#define DCH 32                // d-chunk
#define SMEM_BYTES ((D_*MT + 2*DCH*NT) * 4)   // 128KB + 64KB = 192KB

// ---- scratch (device globals; no allocation allowed) ----
__device__ float g_cn[KC * D_];     // normalized codebook, row-major [K][D]
__device__ float g_cnT[D_ * KC];    // normalized codebook, transposed [D][K]
__device__ int   g_idx[NTOK];
__device__ float g_part[4096];

// ---------------------------------------------------------------------------
__device__ __forceinline__ float blk_reduce_sum(float v, float* sbuf) {
    #pragma unroll
    for (int o = 16; o; o >>= 1) v += __shfl_xor_sync(0xffffffffu, v, o);
    int w = threadIdx.x >> 5;
    if ((threadIdx.x & 31) == 0) sbuf[w] = v;
    __syncthreads();
    if (threadIdx.x < 32) {
        v = (threadIdx.x < (blockDim.x >> 5)) ? sbuf[threadIdx.x] : 0.f;
        #pragma unroll
        for (int o = 4; o; o >>= 1) v += __shfl_xor_sync(0xffffffffu, v, o);
        if (threadIdx.x == 0) sbuf[0] = v;
    }
    __syncthreads();
    return sbuf[0];
}

// ---- codebook row L2-normalize (256 threads == D) --------------------------
__global__ void k_normalize(const float* __restrict__ in, float* __restrict__ out) {
    __shared__ float sbuf[8];
    size_t r = blockIdx.x;
    int t = threadIdx.x;
    float v = in[r * D_ + t];
    float s = blk_reduce_sum(v * v, sbuf);
    float inv = 1.f / fmaxf(sqrtf(s), 1e-12f);
    out[r * D_ + t] = v * inv;
}

// ---- codebook transpose [K][D] -> [D][K] -----------------------------------
__global__ void k_cbT() {
    __shared__ float tile[32][33];
    int k0 = blockIdx.x * 32;
    int d0 = blockIdx.y * 32;
    #pragma unroll
    for (int i = threadIdx.y; i < 32; i += 8)
        tile[i][threadIdx.x] = g_cn[(size_t)(k0 + i) * D_ + d0 + threadIdx.x];
    __syncthreads();
    #pragma unroll
    for (int i = threadIdx.y; i < 32; i += 8)
        g_cnT[(size_t)(d0 + i) * KC + k0 + threadIdx.x] = tile[threadIdx.x][i];
}

// ---- cp.async helpers ------------------------------------------------------
__device__ __forceinline__ void cpa16(void* dst, const void* src) {
    unsigned s = (unsigned)__cvta_generic_to_shared(dst);
    asm volatile("cp.async.cg.shared.global [%0], [%1], 16;\n" :: "r"(s), "l"(src) : "memory");
}
__device__ __forceinline__ void cpa_commit() { asm volatile("cp.async.commit_group;\n" ::: "memory"); }
template <int N>
__device__ __forceinline__ void cpa_wait() { asm volatile("cp.async.wait_group %0;\n" :: "n"(N) : "memory"); }

// ---- fused GEMM (16384 x 8192 x 256) + per-token argmax --------------------
// A = raw tokens (x is already [d][l] per batch), B = normalized codebook^T.
// Token norm is a positive per-token scalar -> argmax-invariant, so skipped.
__global__ void __launch_bounds__(256, 1) k_gemm_argmax(const float* __restrict__ x) {
    extern __shared__ float smem[];
    float* tok_s  = smem;               // [D_][MT]         (128 KB)
    float* code_s = smem + D_ * MT;     // 2 x [DCH][NT]    (64 KB)

    const int tid = threadIdx.x;
    const int tx = tid & 15, ty = tid >> 4;   // tx: 16 code-pair groups, ty: 16 token-octets
    const int b  = blockIdx.x >> 5;           // 32 l-tiles per batch
    const int l0 = (blockIdx.x & 31) * MT;
    const float* xb = x + (size_t)b * D_ * L_ + l0;

    // token tile fill: x is d-major -> direct coalesced copy, [d][m] layout
    for (int i = tid; i < D_ * (MT / 4); i += 256) {
        int d = i >> 5, m4 = i & 31;
        *(float4*)(tok_s + d * MT + m4 * 4) =
            *(const float4*)(xb + (size_t)d * L_ + m4 * 4);
    }

    float bestv[8]; int besti[8];
    #pragma unroll
    for (int i = 0; i < 8; i++) { bestv[i] = -1e30f; besti[i] = 0; }

    const int TOT = (KC / NT) * (D_ / DCH);   // 256 chunks total

    // preload chunk 0 (k0=0, dc=0)
    {
        float* dst = code_s;
        #pragma unroll
        for (int t2 = 0; t2 < 8; t2++) {
            int i = tid + t2 * 256;
            int d = i >> 6, c4 = i & 63;
            cpa16(dst + d * NT + c4 * 4, g_cnT + (size_t)d * KC + c4 * 4);
        }
        cpa_commit();
    }
    int buf = 0;

    for (int k0 = 0; k0 < KC; k0 += NT) {
        unsigned long long acc[8][8];
        #pragma unroll
        for (int i = 0; i < 8; i++)
            #pragma unroll
            for (int j = 0; j < 8; j++) acc[i][j] = 0ull;

        for (int c = 0; c < D_ / DCH; c++) {
            int t = (k0 / NT) * (D_ / DCH) + c;
            if (t + 1 < TOT) {
                int tn = t + 1;
                int nk0 = (tn >> 3) * NT, ndc = (tn & 7) * DCH;
                float* dst = code_s + (buf ^ 1) * (DCH * NT);
                #pragma unroll
                for (int t2 = 0; t2 < 8; t2++) {
                    int i = tid + t2 * 256;
                    int d = i >> 6, c4 = i & 63;
                    cpa16(dst + d * NT + c4 * 4,
                          g_cnT + (size_t)(ndc + d) * KC + nk0 + c4 * 4);
                }
                cpa_commit();
                cpa_wait<1>();
            } else {
                cpa_wait<0>();
            }
            __syncthreads();

            const float* cs = code_s + buf * (DCH * NT);
            const int dcb = c * DCH;
            #pragma unroll 2
            for (int d = 0; d < DCH; d++) {
                float ta[8];
                const float* tp = tok_s + (dcb + d) * MT + ty * 8;
                *(float4*)(ta)     = *(const float4*)(tp);
                *(float4*)(ta + 4) = *(const float4*)(tp + 4);
                unsigned long long ad[8];
                #pragma unroll
                for (int i = 0; i < 8; i++)
                    asm("mov.b64 %0, {%1, %1};" : "=l"(ad[i]) : "f"(ta[i]));
                unsigned long long bp[8];
                const float* cp = cs + d * NT + tx * 2;
                #pragma unroll
                for (int j = 0; j < 8; j++)
                    bp[j] = *(const unsigned long long*)(cp + j * 32);
                #pragma unroll
                for (int i = 0; i < 8; i++)
                    #pragma unroll
                    for (int j = 0; j < 8; j++)
                        asm("fma.rn.f32x2 %0, %1, %2, %0;"
                            : "+l"(acc[i][j]) : "l"(ad[i]), "l"(bp[j]));
            }
            __syncthreads();
            buf ^= 1;
        }

        // fold this 256-code tile into running per-token argmax
        #pragma unroll
        for (int i = 0; i < 8; i++)
            #pragma unroll
            for (int j = 0; j < 8; j++) {
                float lo = __int_as_float((int)(acc[i][j] & 0xffffffffull));
                float hi = __int_as_float((int)(acc[i][j] >> 32));
                int kb = k0 + (j * 16 + tx) * 2;
                if (lo > bestv[i] || (lo == bestv[i] && kb < besti[i])) {
                    bestv[i] = lo; besti[i] = kb;
                }
                if (hi > bestv[i] || (hi == bestv[i] && kb + 1 < besti[i])) {
                    bestv[i] = hi; besti[i] = kb + 1;
                }
            }
    }

    // cross-thread (over tx) argmax reduce; reuse code_s area
    __syncthreads();
    float* rv = code_s;                       // [128][16]
    int*   ri = (int*)(code_s + 128 * 16);    // [128][16]
    #pragma unroll
    for (int i = 0; i < 8; i++) {
        rv[(ty * 8 + i) * 16 + tx] = bestv[i];
        ri[(ty * 8 + i) * 16 + tx] = besti[i];
    }
    __syncthreads();
    if (tid < MT) {
        float bv = -2e30f; int bi = 0;
        #pragma unroll
        for (int t = 0; t < 16; t++) {
            float v = rv[tid * 16 + t]; int ix = ri[tid * 16 + t];
            if (v > bv || (v == bv && ix < bi)) { bv = v; bi = ix; }
        }
        g_idx[b * L_ + l0 + tid] = bi;
    }
}

// ---- output gather + per-block loss partials -------------------------------
__global__ void k_out_loss(const float* __restrict__ x, float* __restrict__ out) {
    __shared__ float sbuf[8];
    int b = blockIdx.x >> 8;
    int d = blockIdx.x & 255;
    int l = blockIdx.y * 1024 + threadIdx.x * 4;
    size_t base = ((size_t)b * D_ + d) * L_;

    float4 xv = *(const float4*)(x + base + l);
    int4  iv  = *(const int4*)(g_idx + b * L_ + l);
    float q0 = g_cn[(size_t)iv.x * D_ + d];
    float q1 = g_cn[(size_t)iv.y * D_ + d];
    float q2 = g_cn[(size_t)iv.z * D_ + d];
    float q3 = g_cn[(size_t)iv.w * D_ + d];
    *(float4*)(out + base + l) = make_float4(q0, q1, q2, q3);

    float e0 = q0 - xv.x, e1 = q1 - xv.y, e2 = q2 - xv.z, e3 = q3 - xv.w;
    float s = blk_reduce_sum(e0*e0 + e1*e1 + e2*e2 + e3*e3, sbuf);
    if (threadIdx.x == 0) g_part[blockIdx.y * 1024 + blockIdx.x] = s;
}

__global__ void k_loss_final(float* __restrict__ out, int pos) {
    __shared__ float sbuf[8];
    float s = 0.f;
    for (int i = threadIdx.x; i < 4096; i += 256) s += g_part[i];
    s = blk_reduce_sum(s, sbuf);
    if (threadIdx.x == 0)
        out[pos] = 0.25f * s / (float)((size_t)NTOK * D_);
}

// ---------------------------------------------------------------------------
extern "C" void kernel_launch(void* const* d_in, const int* in_sizes, int n_in,
                              void* d_out, int out_size) {
    const float* x  = (const float*)d_in[0];   // [4,256,4096]
    const float* cb = (const float*)d_in[1];   // [8192,256]
    float* out = (float*)d_out;

    cudaFuncSetAttribute(k_gemm_argmax,
                         cudaFuncAttributeMaxDynamicSharedMemorySize, SMEM_BYTES);

    void* p_cn = nullptr;
    cudaGetSymbolAddress(&p_cn, g_cn);

    k_normalize<<<KC, 256>>>(cb, (float*)p_cn);
    k_cbT<<<dim3(KC / 32, D_ / 32), dim3(32, 8)>>>();
    k_gemm_argmax<<<NTOK / MT, 256, SMEM_BYTES>>>(x);
    k_out_loss<<<dim3(B_ * D_, 4), 256>>>(x, out);
    if (out_size > NQ)
        k_loss_final<<<1, 256>>>(out, out_size - 1);
}